// round 1
// baseline (speedup 1.0000x reference)
#include <cuda_runtime.h>
#include <math.h>

#define B   256
#define T   128
#define F   64
#define H   512
#define G4  (4*H)
#define O   16

// ---------------- device scratch (no runtime allocation allowed) ----------------
__device__ float g_y0[(size_t)B * T * H];   // layer-0 output sequence (input to layer-1)
__device__ float g_h0[(size_t)B * H];       // ping-pong hidden state
__device__ float g_h1[(size_t)B * H];
__device__ float g_c0[(size_t)B * H];       // ping-pong cell state
__device__ float g_c1[(size_t)B * H];

// ---------------- zero initial state ----------------
__global__ void zero_state_kernel() {
    const int n = B * H;
    for (int i = blockIdx.x * blockDim.x + threadIdx.x; i < n; i += gridDim.x * blockDim.x) {
        g_h0[i] = 0.f;
        g_c0[i] = 0.f;
    }
}

__device__ __forceinline__ float sigf(float x) { return 1.f / (1.f + expf(-x)); }

// ---------------- fused LSTM step ----------------
// Computes, for all (b in [bm0,bm0+32), j in [j0,j0+32)):
//   z_g = sum_k xin[b,k]*Wx[k, g*H+j]  +  sum_k hprev[b,k]*U[k, g*H+j]  +  bias[g*H+j]
//   c   = sig(z_f)*cprev + sig(z_i)*tanh(z_g)
//   h   = sig(z_o)*tanh(c)
// Gate order (Keras): i, f, g, o  ->  column blocks 0,H,2H,3H.
__global__ void __launch_bounds__(256) lstm_step_kernel(
    const float* __restrict__ xin, size_t xin_stride, int xin_k, const float* __restrict__ Wx,
    const float* __restrict__ hprev, const float* __restrict__ U,
    const float* __restrict__ bias,
    const float* __restrict__ cprev,
    float* __restrict__ hnext, float* __restrict__ cnext,
    float* __restrict__ ycopy)   // optional: also store h at ycopy[b*(T*H)+j]
{
    __shared__ float sX[32][36];        // [m_local][kk]   (36: pad, keeps float4 stores aligned)
    __shared__ float sW[4][32][32];     // [gate][kk][jj]

    const int tid = threadIdx.x;
    const int tx  = tid & 15;           // -> 2 hidden units (2*tx, 2*tx+1)
    const int ty  = tid >> 4;           // -> 2 batch rows   (2*ty, 2*ty+1)
    const int bm0 = blockIdx.x * 32;
    const int j0  = blockIdx.y * 32;

    float acc[2][4][2];
    #pragma unroll
    for (int m = 0; m < 2; ++m)
        #pragma unroll
        for (int g = 0; g < 4; ++g)
            #pragma unroll
            for (int jj = 0; jj < 2; ++jj) acc[m][g][jj] = 0.f;

    // phase 0: X = xin (K = xin_k, matrix Wx) ; phase 1: X = hprev (K = H, matrix U)
    #pragma unroll 1
    for (int phase = 0; phase < 2; ++phase) {
        const float* Xp   = phase ? hprev : xin;
        const float* Wp   = phase ? U : Wx;
        const int    Ktot = phase ? H : xin_k;
        const size_t xs   = phase ? (size_t)H : xin_stride;

        #pragma unroll 1
        for (int k0 = 0; k0 < Ktot; k0 += 32) {
            // ---- stage X chunk: 32 rows x 32 k  (each thread: one float4) ----
            {
                const int m  = tid >> 3;          // 0..31
                const int kk = (tid & 7) * 4;     // 0,4,...,28
                const float* src = Xp + (size_t)(bm0 + m) * xs + (size_t)k0 + kk;
                float4 v;
                if (k0 + kk + 3 < Ktot) {
                    v = *(const float4*)src;
                } else {
                    v.x = (k0 + kk + 0 < Ktot) ? src[0] : 0.f;
                    v.y = (k0 + kk + 1 < Ktot) ? src[1] : 0.f;
                    v.z = (k0 + kk + 2 < Ktot) ? src[2] : 0.f;
                    v.w = (k0 + kk + 3 < Ktot) ? src[3] : 0.f;
                }
                *(float4*)&sX[m][kk] = v;
            }
            // ---- stage W chunk: 4 gates x 32 k x 32 j  (each thread: 16 scalars) ----
            #pragma unroll
            for (int i = 0; i < 16; ++i) {
                const int q  = tid + i * 256;
                const int jj = q & 31;
                const int kk = (q >> 5) & 31;
                const int g  = q >> 10;
                float v = 0.f;
                if (k0 + kk < Ktot)
                    v = Wp[(size_t)(k0 + kk) * G4 + (size_t)g * H + j0 + jj];
                sW[g][kk][jj] = v;
            }
            __syncthreads();

            // ---- MAC ----
            #pragma unroll
            for (int kk = 0; kk < 32; ++kk) {
                const float a0 = sX[2 * ty + 0][kk];
                const float a1 = sX[2 * ty + 1][kk];
                #pragma unroll
                for (int g = 0; g < 4; ++g) {
                    const float2 w = *(const float2*)&sW[g][kk][2 * tx];
                    acc[0][g][0] = fmaf(a0, w.x, acc[0][g][0]);
                    acc[0][g][1] = fmaf(a0, w.y, acc[0][g][1]);
                    acc[1][g][0] = fmaf(a1, w.x, acc[1][g][0]);
                    acc[1][g][1] = fmaf(a1, w.y, acc[1][g][1]);
                }
            }
            __syncthreads();
        }
    }

    // ---- epilogue: gates + state update ----
    #pragma unroll
    for (int mm = 0; mm < 2; ++mm) {
        const int b = bm0 + 2 * ty + mm;
        #pragma unroll
        for (int jj = 0; jj < 2; ++jj) {
            const int j = j0 + 2 * tx + jj;
            const float zi = acc[mm][0][jj] + bias[0 * H + j];
            const float zf = acc[mm][1][jj] + bias[1 * H + j];
            const float zg = acc[mm][2][jj] + bias[2 * H + j];
            const float zo = acc[mm][3][jj] + bias[3 * H + j];
            const float c  = sigf(zf) * cprev[(size_t)b * H + j] + sigf(zi) * tanhf(zg);
            const float h  = sigf(zo) * tanhf(c);
            cnext[(size_t)b * H + j] = c;
            hnext[(size_t)b * H + j] = h;
            if (ycopy) ycopy[(size_t)b * ((size_t)T * H) + j] = h;
        }
    }
}

// ---------------- final FC + tile over future_seq_len ----------------
__global__ void fc_tile_kernel(const float* __restrict__ d1,
                               const float* __restrict__ fcW,   // [H, O]
                               const float* __restrict__ fcb,   // [O]
                               float* __restrict__ out, int fut)
{
    __shared__ float sd[H];
    __shared__ float part[16][16];   // [seg][o]
    __shared__ float fin[O];

    const int b   = blockIdx.x;
    const int tid = threadIdx.x;

    for (int i = tid; i < H; i += 256) sd[i] = d1[(size_t)b * H + i];
    __syncthreads();

    const int o   = tid & 15;
    const int seg = tid >> 4;       // 16 segments of 32 k each
    float s = 0.f;
    #pragma unroll
    for (int k = seg * 32; k < seg * 32 + 32; ++k)
        s = fmaf(sd[k], fcW[(size_t)k * O + o], s);
    part[seg][o] = s;
    __syncthreads();

    if (tid < O) {
        float t = fcb[tid];
        #pragma unroll
        for (int sg = 0; sg < 16; ++sg) t += part[sg][tid];
        fin[tid] = t;
    }
    __syncthreads();

    for (int i = tid; i < fut * O; i += 256)
        out[(size_t)b * fut * O + i] = fin[i & 15];
}

// ---------------- host launcher ----------------
extern "C" void kernel_launch(void* const* d_in, const int* in_sizes, int n_in,
                              void* d_out, int out_size)
{
    const float* inp    = (const float*)d_in[0];
    // d_in[1] = future_seq_len (int scalar) — derived from out_size instead
    const float* enc_W0 = (const float*)d_in[2];
    const float* enc_U0 = (const float*)d_in[3];
    const float* enc_b0 = (const float*)d_in[4];
    const float* enc_W1 = (const float*)d_in[5];
    const float* enc_U1 = (const float*)d_in[6];
    const float* enc_b1 = (const float*)d_in[7];
    const float* dec_W0 = (const float*)d_in[8];
    const float* dec_U0 = (const float*)d_in[9];
    const float* dec_b0 = (const float*)d_in[10];
    const float* dec_W1 = (const float*)d_in[11];
    const float* dec_U1 = (const float*)d_in[12];
    const float* dec_b1 = (const float*)d_in[13];
    const float* fc_W   = (const float*)d_in[14];
    const float* fc_b   = (const float*)d_in[15];
    float* out = (float*)d_out;

    float *h0, *h1, *c0, *c1, *y0;
    cudaGetSymbolAddress((void**)&h0, g_h0);
    cudaGetSymbolAddress((void**)&h1, g_h1);
    cudaGetSymbolAddress((void**)&c0, g_c0);
    cudaGetSymbolAddress((void**)&c1, g_c1);
    cudaGetSymbolAddress((void**)&y0, g_y0);

    zero_state_kernel<<<128, 256>>>();

    const dim3 grid(B / 32, H / 32);   // 8 x 16 = 128 CTAs

    // ---- encoder layer 0: z = x_t@W0 + h@U0 + b0 ----
    for (int t = 0; t < T; ++t) {
        const float* hp = (t & 1) ? h1 : h0;
        float*       hn = (t & 1) ? h0 : h1;
        const float* cp = (t & 1) ? c1 : c0;
        float*       cn = (t & 1) ? c0 : c1;
        lstm_step_kernel<<<grid, 256>>>(
            inp + (size_t)t * F, (size_t)T * F, F, enc_W0,
            hp, enc_U0, enc_b0, cp, hn, cn,
            y0 + (size_t)t * H);
    }
    // T even -> layer-0 finals land in h0/c0; layer-1 initial state = layer-0 finals.

    // ---- encoder layer 1: z = y0_t@W1 + h@U1 + b1 ----
    for (int t = 0; t < T; ++t) {
        const float* hp = (t & 1) ? h1 : h0;
        float*       hn = (t & 1) ? h0 : h1;
        const float* cp = (t & 1) ? c1 : c0;
        float*       cn = (t & 1) ? c0 : c1;
        lstm_step_kernel<<<grid, 256>>>(
            y0 + (size_t)t * H, (size_t)T * H, H, enc_W1,
            hp, enc_U1, enc_b1, cp, hn, cn,
            nullptr);
    }
    // finals in h0/c0

    // ---- decoder step 0: x = inp[:, T-1, :O], state from encoder ----
    lstm_step_kernel<<<grid, 256>>>(
        inp + (size_t)(T - 1) * F, (size_t)T * F, O, dec_W0,
        h0, dec_U0, dec_b0, c0, h1, c1,
        nullptr);

    // ---- decoder step 1: x = d0 (== h1), initial state (h1, c1) ----
    lstm_step_kernel<<<grid, 256>>>(
        h1, (size_t)H, H, dec_W1,
        h1, dec_U1, dec_b1, c1, h0, c0,
        nullptr);

    // ---- FC + tile ----
    const int fut = out_size / (B * O);
    fc_tile_kernel<<<B, 256>>>(h0, fc_W, fc_b, out, fut);
}

// round 3
// speedup vs baseline: 4.1805x; 4.1805x over previous
#include <cuda_runtime.h>
#include <cuda_bf16.h>
#include <cstdint>
#include <math.h>

#define Bz   256
#define Tz   128
#define Fz   64
#define Hz   512
#define Oz   16
#define GC   2048

// Per-layer concatenated-K sizes (Kx + H)
#define KT_E0  576
#define KT_E1  1024
#define KT_D0  528
#define KT_D1  1024
#define WOFF_E0 0
#define WOFF_E1 (WOFF_E0 + (size_t)GC*KT_E0)
#define WOFF_D0 (WOFF_E1 + (size_t)GC*KT_E1)
#define WOFF_D1 (WOFF_D0 + (size_t)GC*KT_D0)
#define WTOTAL  (WOFF_D1 + (size_t)GC*KT_D1)

// smem buffer geometry (bf16 tiles, rows padded to 72 elems = 144B, 16B-aligned)
#define ROWE 72
#define ROWBYTES (ROWE*2)          // 144
#define ARR_BYTES (64*ROWBYTES)    // 9216 per 64x64 tile
#define BUF_BYTES (4*ARR_BYTES)    // A_hi A_lo B_hi B_lo = 36864
#define SMEM_BYTES (2*BUF_BYTES)   // 73728 (double buffer; Z epilogue reuses buf0)

// ------------------------- device scratch -------------------------
__device__ __nv_bfloat16 g_xh[(size_t)Bz*Tz*Fz];
__device__ __nv_bfloat16 g_xl[(size_t)Bz*Tz*Fz];
__device__ __nv_bfloat16 g_yh[(size_t)Bz*Tz*Hz];
__device__ __nv_bfloat16 g_yl[(size_t)Bz*Tz*Hz];
__device__ __nv_bfloat16 g_wh[WTOTAL];
__device__ __nv_bfloat16 g_wl[WTOTAL];
__device__ __nv_bfloat16 g_hh[2*(size_t)Bz*Hz];
__device__ __nv_bfloat16 g_hl[2*(size_t)Bz*Hz];
__device__ float         g_c [2*(size_t)Bz*Hz];   // hidden-major: c[j*B + b]

// ------------------------- PTX helpers -------------------------
__device__ __forceinline__ uint32_t smem_u32(const void* p) {
    uint32_t a;
    asm("{ .reg .u64 t; cvta.to.shared.u64 t, %1; cvt.u32.u64 %0, t; }" : "=r"(a) : "l"(p));
    return a;
}
__device__ __forceinline__ void cp16(uint32_t dst, const void* src, int sz) {
    asm volatile("cp.async.cg.shared.global [%0], [%1], 16, %2;"
                 :: "r"(dst), "l"(src), "r"(sz) : "memory");
}
#define CP_COMMIT() asm volatile("cp.async.commit_group;" ::: "memory")
#define CP_WAIT(n)  asm volatile("cp.async.wait_group %0;" :: "n"(n) : "memory")

__device__ __forceinline__ void ldm_x4(uint32_t* r, uint32_t addr) {
    asm volatile("ldmatrix.sync.aligned.m8n8.x4.shared.b16 {%0,%1,%2,%3}, [%4];"
                 : "=r"(r[0]), "=r"(r[1]), "=r"(r[2]), "=r"(r[3]) : "r"(addr));
}
__device__ __forceinline__ void mma16816(float* c, const uint32_t* a, uint32_t b0, uint32_t b1) {
    asm volatile("mma.sync.aligned.m16n8k16.row.col.f32.bf16.bf16.f32 "
                 "{%0,%1,%2,%3}, {%4,%5,%6,%7}, {%8,%9}, {%0,%1,%2,%3};"
                 : "+f"(c[0]), "+f"(c[1]), "+f"(c[2]), "+f"(c[3])
                 : "r"(a[0]), "r"(a[1]), "r"(a[2]), "r"(a[3]), "r"(b0), "r"(b1));
}
__device__ __forceinline__ float sigf(float x) { return 1.f / (1.f + expf(-x)); }

// ------------------------- staging (cp.async) -------------------------
// Buffer layout: [A_hi | A_lo | B_hi | B_lo], each 64 rows x 144B.
__device__ __forceinline__ void stage_chunk(
    uint32_t bufb, int k0, int Kx, int Ktot, int xs,
    const __nv_bfloat16* __restrict__ xh, const __nv_bfloat16* __restrict__ xl,
    const __nv_bfloat16* __restrict__ hh, const __nv_bfloat16* __restrict__ hl,
    const __nv_bfloat16* __restrict__ wh, const __nv_bfloat16* __restrict__ wl,
    int m0, int n0, int tid)
{
    #pragma unroll
    for (int i = 0; i < 8; ++i) {
        const int v   = tid + i * 256;
        const int sec = v >> 9;              // 0:A_hi 1:A_lo 2:B_hi 3:B_lo
        const int r   = (v >> 3) & 63;
        const int kk  = (v & 7) * 8;
        const int k   = k0 + kk;
        const uint32_t dst = bufb + (uint32_t)sec * ARR_BYTES + (uint32_t)r * ROWBYTES + (uint32_t)kk * 2;
        const __nv_bfloat16* src;
        int sz = 16;
        if (sec < 2) {
            const __nv_bfloat16* xb = sec ? xl : xh;
            const __nv_bfloat16* hb = sec ? hl : hh;
            const int b = m0 + r;
            if (k < Kx)        src = xb + (size_t)b * xs + k;
            else if (k < Ktot) src = hb + (size_t)b * Hz + (k - Kx);
            else             { src = xb; sz = 0; }
        } else {
            const __nv_bfloat16* wb = (sec == 2) ? wh : wl;
            if (k < Ktot) src = wb + (size_t)(n0 + r) * Ktot + k;
            else        { src = wb; sz = 0; }
        }
        cp16(dst, src, sz);
    }
}

// ------------------------- fused LSTM step (mma.sync bf16) -------------------------
// Z[64m x 64n] = [x|h](hi/lo) @ Wt(hi/lo), Wt gate-interleaved: col 4j+g.
// Epilogue: gates + state update, fused.
__global__ void __launch_bounds__(256, 1)
lstm_step_mma(
    const __nv_bfloat16* __restrict__ xh, const __nv_bfloat16* __restrict__ xl, int xs, int Kx,
    const __nv_bfloat16* __restrict__ hh, const __nv_bfloat16* __restrict__ hl,
    const __nv_bfloat16* __restrict__ wh, const __nv_bfloat16* __restrict__ wl, int Ktot,
    const float* __restrict__ bias,
    const float* __restrict__ cprev, float* __restrict__ cnext,
    __nv_bfloat16* __restrict__ hh_n, __nv_bfloat16* __restrict__ hl_n,
    __nv_bfloat16* __restrict__ yh, __nv_bfloat16* __restrict__ yl)
{
    extern __shared__ char smem[];
    const uint32_t sb  = smem_u32(smem);
    const int tid  = threadIdx.x;
    const int wid  = tid >> 5;
    const int lane = tid & 31;
    const int wm   = wid >> 1;          // 0..3 (m warp)
    const int wn   = wid & 1;           // 0..1 (n warp)
    const int m0   = blockIdx.x * 64;
    const int n0   = blockIdx.y * 64;
    const int NCH  = (Ktot + 63) >> 6;

    float acc[4][4];
    #pragma unroll
    for (int nt = 0; nt < 4; ++nt)
        #pragma unroll
        for (int q = 0; q < 4; ++q) acc[nt][q] = 0.f;

    // ldmatrix address bases (byte offsets within an array)
    // A: row = wm*16 + (lane&15), col byte = (lane>=16 ? 16 : 0) + kt*32
    const uint32_t aOff = (uint32_t)(wm * 16 + (lane & 15)) * ROWBYTES + ((lane >> 4) << 4);
    // B: row = wn*32 + p*16 + (lane&7) + (lane>=16 ? 8 : 0), col byte = ((lane>>3)&1)*16 + kt*32
    const uint32_t bRow = (uint32_t)(wn * 32 + (lane & 7) + ((lane >> 4) << 3));
    const uint32_t bOff0 = bRow * ROWBYTES + (((lane >> 3) & 1) << 4);
    const uint32_t bOff1 = bOff0 + 16u * ROWBYTES;

    stage_chunk(sb, 0, Kx, Ktot, xs, xh, xl, hh, hl, wh, wl, m0, n0, tid);
    CP_COMMIT();

    for (int ch = 0; ch < NCH; ++ch) {
        const uint32_t buf = sb + (uint32_t)(ch & 1) * BUF_BYTES;
        if (ch + 1 < NCH) {
            stage_chunk(sb + (uint32_t)((ch + 1) & 1) * BUF_BYTES, (ch + 1) * 64,
                        Kx, Ktot, xs, xh, xl, hh, hl, wh, wl, m0, n0, tid);
            CP_COMMIT();
            CP_WAIT(1);
        } else {
            CP_WAIT(0);
        }
        __syncthreads();

        const uint32_t sAh = buf, sAl = buf + ARR_BYTES;
        const uint32_t sBh = buf + 2 * ARR_BYTES, sBl = buf + 3 * ARR_BYTES;
        #pragma unroll
        for (int kt = 0; kt < 4; ++kt) {
            uint32_t ah[4], al[4];
            ldm_x4(ah, sAh + aOff + kt * 32);
            ldm_x4(al, sAl + aOff + kt * 32);
            #pragma unroll
            for (int p = 0; p < 2; ++p) {
                const uint32_t bo = (p ? bOff1 : bOff0) + kt * 32;
                uint32_t bh[4], bl[4];
                ldm_x4(bh, sBh + bo);
                ldm_x4(bl, sBl + bo);
                mma16816(acc[2*p],   ah, bh[0], bh[1]);
                mma16816(acc[2*p],   ah, bl[0], bl[1]);
                mma16816(acc[2*p],   al, bh[0], bh[1]);
                mma16816(acc[2*p+1], ah, bh[2], bh[3]);
                mma16816(acc[2*p+1], ah, bl[2], bl[3]);
                mma16816(acc[2*p+1], al, bh[2], bh[3]);
            }
        }
        __syncthreads();
    }

    // ---- epilogue: Z -> smem, gather gates, update state ----
    float* Zs = reinterpret_cast<float*>(smem);   // [64][72]
    {
        const int r0 = wm * 16 + (lane >> 2);
        #pragma unroll
        for (int nt = 0; nt < 4; ++nt) {
            const int n = wn * 32 + nt * 8 + 2 * (lane & 3);
            Zs[r0 * ROWE + n]       = acc[nt][0];
            Zs[r0 * ROWE + n + 1]   = acc[nt][1];
            Zs[(r0+8) * ROWE + n]   = acc[nt][2];
            Zs[(r0+8) * ROWE + n+1] = acc[nt][3];
        }
    }
    __syncthreads();

    const int m  = tid >> 2;
    const int jq = tid & 3;
    const int b  = m0 + m;
    const int jb = (n0 >> 2) + jq * 4;

    __nv_bfloat16 ohv[4], olv[4];
    #pragma unroll
    for (int u = 0; u < 4; ++u) {
        const float4 z = *reinterpret_cast<const float4*>(&Zs[m * ROWE + jq * 16 + u * 4]);
        const int j = jb + u;
        const float zi = z.x + bias[          j];
        const float zf = z.y + bias[Hz      + j];
        const float zg = z.z + bias[2*Hz    + j];
        const float zo = z.w + bias[3*Hz    + j];
        const float cp = cprev[(size_t)j * Bz + b];
        const float c  = sigf(zf) * cp + sigf(zi) * tanhf(zg);
        const float h  = sigf(zo) * tanhf(c);
        cnext[(size_t)j * Bz + b] = c;
        ohv[u] = __float2bfloat16(h);
        olv[u] = __float2bfloat16(h - __bfloat162float(ohv[u]));
    }
    *reinterpret_cast<uint2*>(hh_n + (size_t)b * Hz + jb) = *reinterpret_cast<uint2*>(ohv);
    *reinterpret_cast<uint2*>(hl_n + (size_t)b * Hz + jb) = *reinterpret_cast<uint2*>(olv);
    if (yh) {
        *reinterpret_cast<uint2*>(yh + (size_t)b * Hz + jb) = *reinterpret_cast<uint2*>(ohv);
        *reinterpret_cast<uint2*>(yl + (size_t)b * Hz + jb) = *reinterpret_cast<uint2*>(olv);
    }
}

// ------------------------- prep kernels -------------------------
__global__ void split_inp_kernel(const float* __restrict__ inp) {
    const size_t n = (size_t)Bz * Tz * Fz;
    for (size_t i = blockIdx.x * blockDim.x + threadIdx.x; i < n; i += (size_t)gridDim.x * blockDim.x) {
        const float v = inp[i];
        const __nv_bfloat16 hi = __float2bfloat16(v);
        g_xh[i] = hi;
        g_xl[i] = __float2bfloat16(v - __bfloat162float(hi));
    }
}

// Wt[c][k], c = 4j+g ; source col = g*H + j ; k<Kx -> W, else U
__global__ void prep_w_kernel(const float* __restrict__ W, const float* __restrict__ U,
                              int Kx, int Ktot, __nv_bfloat16* __restrict__ oh, __nv_bfloat16* __restrict__ ol) {
    const size_t n = (size_t)GC * Ktot;
    for (size_t i = blockIdx.x * blockDim.x + threadIdx.x; i < n; i += (size_t)gridDim.x * blockDim.x) {
        const int c = (int)(i / Ktot);
        const int k = (int)(i % Ktot);
        const int col = (c & 3) * Hz + (c >> 2);
        const float v = (k < Kx) ? W[(size_t)k * GC + col] : U[(size_t)(k - Kx) * GC + col];
        const __nv_bfloat16 hi = __float2bfloat16(v);
        oh[i] = hi;
        ol[i] = __float2bfloat16(v - __bfloat162float(hi));
    }
}

__global__ void zero_state_kernel() {
    const int n = Bz * Hz;
    for (int i = blockIdx.x * blockDim.x + threadIdx.x; i < n; i += gridDim.x * blockDim.x) {
        g_c[i]  = 0.f;
        g_hh[i] = __float2bfloat16(0.f);
        g_hl[i] = __float2bfloat16(0.f);
    }
}

// ------------------------- FC + tile -------------------------
__global__ void fc_tile_kernel(const __nv_bfloat16* __restrict__ dh, const __nv_bfloat16* __restrict__ dl,
                               const float* __restrict__ fcW, const float* __restrict__ fcb,
                               float* __restrict__ out, int fut) {
    __shared__ float sd[Hz];
    __shared__ float part[16][16];
    __shared__ float fin[Oz];
    const int b = blockIdx.x, tid = threadIdx.x;
    for (int i = tid; i < Hz; i += 256)
        sd[i] = __bfloat162float(dh[(size_t)b * Hz + i]) + __bfloat162float(dl[(size_t)b * Hz + i]);
    __syncthreads();
    const int o = tid & 15, seg = tid >> 4;
    float s = 0.f;
    #pragma unroll
    for (int k = seg * 32; k < seg * 32 + 32; ++k)
        s = fmaf(sd[k], fcW[(size_t)k * Oz + o], s);
    part[seg][o] = s;
    __syncthreads();
    if (tid < Oz) {
        float t = fcb[tid];
        #pragma unroll
        for (int sg = 0; sg < 16; ++sg) t += part[sg][tid];
        fin[tid] = t;
    }
    __syncthreads();
    for (int i = tid; i < fut * Oz; i += 256)
        out[(size_t)b * fut * Oz + i] = fin[i & 15];
}

// ------------------------- host launcher -------------------------
extern "C" void kernel_launch(void* const* d_in, const int* in_sizes, int n_in,
                              void* d_out, int out_size)
{
    const float* inp    = (const float*)d_in[0];
    const float* enc_W0 = (const float*)d_in[2];
    const float* enc_U0 = (const float*)d_in[3];
    const float* enc_b0 = (const float*)d_in[4];
    const float* enc_W1 = (const float*)d_in[5];
    const float* enc_U1 = (const float*)d_in[6];
    const float* enc_b1 = (const float*)d_in[7];
    const float* dec_W0 = (const float*)d_in[8];
    const float* dec_U0 = (const float*)d_in[9];
    const float* dec_b0 = (const float*)d_in[10];
    const float* dec_W1 = (const float*)d_in[11];
    const float* dec_U1 = (const float*)d_in[12];
    const float* dec_b1 = (const float*)d_in[13];
    const float* fc_W   = (const float*)d_in[14];
    const float* fc_b   = (const float*)d_in[15];
    float* out = (float*)d_out;

    static bool attr_set = false;
    if (!attr_set) {
        cudaFuncSetAttribute(lstm_step_mma, cudaFuncAttributeMaxDynamicSharedMemorySize, SMEM_BYTES);
        attr_set = true;
    }

    __nv_bfloat16 *xh, *xl, *yh, *yl, *wh, *wl, *hh, *hl;
    float* cc;
    cudaGetSymbolAddress((void**)&xh, g_xh);
    cudaGetSymbolAddress((void**)&xl, g_xl);
    cudaGetSymbolAddress((void**)&yh, g_yh);
    cudaGetSymbolAddress((void**)&yl, g_yl);
    cudaGetSymbolAddress((void**)&wh, g_wh);
    cudaGetSymbolAddress((void**)&wl, g_wl);
    cudaGetSymbolAddress((void**)&hh, g_hh);
    cudaGetSymbolAddress((void**)&hl, g_hl);
    cudaGetSymbolAddress((void**)&cc, g_c);
    const size_t SH = (size_t)Bz * Hz;

    split_inp_kernel<<<1024, 256>>>(inp);
    prep_w_kernel<<<2048, 256>>>(enc_W0, enc_U0,  Fz, KT_E0, wh + WOFF_E0, wl + WOFF_E0);
    prep_w_kernel<<<2048, 256>>>(enc_W1, enc_U1,  Hz, KT_E1, wh + WOFF_E1, wl + WOFF_E1);
    prep_w_kernel<<<2048, 256>>>(dec_W0, dec_U0,  Oz, KT_D0, wh + WOFF_D0, wl + WOFF_D0);
    prep_w_kernel<<<2048, 256>>>(dec_W1, dec_U1,  Hz, KT_D1, wh + WOFF_D1, wl + WOFF_D1);
    zero_state_kernel<<<256, 256>>>();

    const dim3 grid(Bz / 64, GC / 64);   // 4 x 32 = 128 CTAs

    // encoder layer 0 (Kx=64, x from inp splits); writes y0 splits
    for (int t = 0; t < Tz; ++t) {
        const int p = t & 1, q = p ^ 1;
        lstm_step_mma<<<grid, 256, SMEM_BYTES>>>(
            xh + (size_t)t * Fz, xl + (size_t)t * Fz, Tz * Fz, Fz,
            hh + p * SH, hl + p * SH, wh + WOFF_E0, wl + WOFF_E0, KT_E0, enc_b0,
            cc + p * SH, cc + q * SH, hh + q * SH, hl + q * SH,
            yh + (size_t)t * SH, yl + (size_t)t * SH);
    }
    // encoder layer 1 (Kx=512, x from y0 splits); init state = layer0 finals (idx 0)
    for (int t = 0; t < Tz; ++t) {
        const int p = t & 1, q = p ^ 1;
        lstm_step_mma<<<grid, 256, SMEM_BYTES>>>(
            yh + (size_t)t * SH, yl + (size_t)t * SH, Hz, Hz,
            hh + p * SH, hl + p * SH, wh + WOFF_E1, wl + WOFF_E1, KT_E1, enc_b1,
            cc + p * SH, cc + q * SH, hh + q * SH, hl + q * SH,
            nullptr, nullptr);
    }
    // decoder step 0: x = inp[:, T-1, :16] (Kx=16), state idx0 -> idx1
    lstm_step_mma<<<grid, 256, SMEM_BYTES>>>(
        xh + (size_t)(Tz - 1) * Fz, xl + (size_t)(Tz - 1) * Fz, Tz * Fz, Oz,
        hh, hl, wh + WOFF_D0, wl + WOFF_D0, KT_D0, dec_b0,
        cc, cc + SH, hh + SH, hl + SH,
        nullptr, nullptr);
    // decoder step 1: x = d0 = h idx1 (Kx=512), state idx1 -> idx0
    lstm_step_mma<<<grid, 256, SMEM_BYTES>>>(
        hh + SH, hl + SH, Hz, Hz,
        hh + SH, hl + SH, wh + WOFF_D1, wl + WOFF_D1, KT_D1, dec_b1,
        cc + SH, cc, hh, hl,
        nullptr, nullptr);

    const int fut = out_size / (Bz * Oz);
    fc_tile_kernel<<<Bz, 256>>>(hh, hl, fc_W, fc_b, out, fut);
}